// round 2
// baseline (speedup 1.0000x reference)
#include <cuda_runtime.h>
#include <math.h>

#define NN 2048
#define MM 32
#define GBLK 128              // blocks in the row-pass kernels
#define RBLK (NN / GBLK)      // 16 rows per block
#define NW 8                  // warps per block (256 threads)
#define RPW (RBLK / NW)       // 2 rows per warp

// ---- scratch (no allocations allowed) ----
__device__ float  g_pmax[GBLK][MM];          // per-block per-column max partials
__device__ double g_pmom[GBLK][10][MM];      // per-block partial weighted moments
__device__ float  g_max[MM];                 // per-column max of (expr - tr)
__device__ float  g_scale;                   // 1 / (2*sigma*sqrt(2))
__device__ double g_bco[11][MM];             // rows 0..9: poly coeffs b_m; row 10: W = M0
__device__ double g_part[GBLK];              // per-block partial loss sums

// 0.5*erf(d) = sum_n Cn * d^(2n+1), |d| <= 0.3536, trunc err < 5e-9
__device__ __constant__ double d_C[5] = {
     0.5641895835477563,
    -0.18806319451591878,
     0.05641895835477563,
    -0.013433085322565627,
     0.0026119888127211866
};

__device__ __forceinline__ double binomd(int n, int k) {
    double r = 1.0;
    for (int i = 1; i <= k; ++i) r = r * (double)(n - k + i) / (double)i;
    return r;
}

// ---------------------------------------------------------------------------
// K1: per-block per-column max of diff = expr - tr. Coalesced: lane = column.
// ---------------------------------------------------------------------------
__global__ void __launch_bounds__(256) k1_pmax(const float* __restrict__ expr,
                                               const float* __restrict__ tr) {
    const int warp = threadIdx.x >> 5, lane = threadIdx.x & 31;
    const int row0 = blockIdx.x * RBLK + warp * RPW;
    float mx = -1e30f;
#pragma unroll
    for (int r = 0; r < RPW; ++r) {
        int idx = (row0 + r) * MM + lane;
        mx = fmaxf(mx, expr[idx] - tr[idx]);
    }
    __shared__ float sm[NW][MM];
    sm[warp][lane] = mx;
    __syncthreads();
    if (warp == 0) {
        float m = sm[0][lane];
#pragma unroll
        for (int i = 1; i < NW; ++i) m = fmaxf(m, sm[i][lane]);
        g_pmax[blockIdx.x][lane] = m;
    }
}

// ---------------------------------------------------------------------------
// K2: finish the column max, then per-block partial weighted moments
//     M_p = sum_a w_a * x_a^p (p=0..9) in double.  x = exp(diff-mx)*scale.
// ---------------------------------------------------------------------------
__global__ void __launch_bounds__(256) k2_moments(const float* __restrict__ risk,
                                                  const float* __restrict__ expr,
                                                  const float* __restrict__ tr,
                                                  const float* __restrict__ sigma) {
    const int tid = threadIdx.x;
    const int warp = tid >> 5, lane = tid & 31;
    __shared__ float  smax[MM];
    __shared__ float  sscale;
    __shared__ double smom[NW][10][MM];   // 20 KB

    if (tid < 32) {
        float m = -1e30f;
        for (int i = 0; i < GBLK; ++i) m = fmaxf(m, g_pmax[i][tid]);
        smax[tid] = m;
        if (blockIdx.x == 0) g_max[tid] = m;
    }
    if (tid == 0) {
        float sc = 1.0f / (2.0f * sigma[0] * sqrtf(2.0f));
        sscale = sc;
        if (blockIdx.x == 0) g_scale = sc;
    }
    __syncthreads();

    const int row0 = blockIdx.x * RBLK + warp * RPW;
    double m[10];
#pragma unroll
    for (int q = 0; q < 10; ++q) m[q] = 0.0;
#pragma unroll
    for (int r = 0; r < RPW; ++r) {
        int   idx = (row0 + r) * MM + lane;
        float w   = expf(risk[idx]);
        float x   = expf(expr[idx] - tr[idx] - smax[lane]) * sscale;
        double xd = (double)x;
        double p  = (double)w;
#pragma unroll
        for (int q = 0; q < 10; ++q) { m[q] += p; p *= xd; }
    }
#pragma unroll
    for (int q = 0; q < 10; ++q) smom[warp][q][lane] = m[q];
    __syncthreads();

    for (int q = warp; q < 10; q += NW) {
        double s = smom[0][q][lane];
#pragma unroll
        for (int i = 1; i < NW; ++i) s += smom[i][q][lane];
        g_pmom[blockIdx.x][q][lane] = s;
    }
}

// ---------------------------------------------------------------------------
// K3: reduce moment partials and expand into monomial coefficients:
//     S(x) = sum_m b_m x^m,
//     b_m  = sum_n C_n * binom(2n+1, m) * (-1)^(2n+1-m) * M_(2n+1-m)
// One block, 320 threads: thread = (m = t/32, k = t%32).
// ---------------------------------------------------------------------------
__global__ void __launch_bounds__(320) k3_coeffs() {
    const int t = threadIdx.x;
    const int k = t & 31, m = t >> 5;   // m in 0..9
    __shared__ double Ms[10][MM];

    double M = 0.0;
    for (int b = 0; b < GBLK; ++b) M += g_pmom[b][m][k];
    Ms[m][k] = M;
    __syncthreads();

    double bm = 0.0;
#pragma unroll
    for (int n = 0; n < 5; ++n) {
        int L = 2 * n + 1;
        if (L >= m) {
            double s = ((L - m) & 1) ? -1.0 : 1.0;
            bm += d_C[n] * binomd(L, m) * s * Ms[L - m][k];
        }
    }
    g_bco[m][k] = bm;
    if (m == 0) g_bco[10][k] = Ms[0][k];   // W_k
}

// ---------------------------------------------------------------------------
// K4: per-element evaluation + per-block partial loss.
//     cumsum = 0.5*(W + w_j) - S(x_j);  val = (risk - log(cumsum)) * ev
// ---------------------------------------------------------------------------
__global__ void __launch_bounds__(256) k4_eval(const float* __restrict__ risk,
                                               const float* __restrict__ expr,
                                               const float* __restrict__ tr,
                                               const float* __restrict__ ev) {
    const int tid = threadIdx.x;
    const int warp = tid >> 5, lane = tid & 31;

    double bb[11];
#pragma unroll
    for (int q = 0; q < 11; ++q) bb[q] = g_bco[q][lane];
    const float mx = g_max[lane];
    const float sc = g_scale;

    const int row0 = blockIdx.x * RBLK + warp * RPW;
    double acc = 0.0;
#pragma unroll
    for (int r = 0; r < RPW; ++r) {
        int    idx = (row0 + r) * MM + lane;
        float  rv  = risk[idx];
        float  w   = expf(rv);
        float  x   = expf(expr[idx] - tr[idx] - mx) * sc;
        double xd  = (double)x;
        double s   = bb[9];
#pragma unroll
        for (int q = 8; q >= 0; --q) s = s * xd + bb[q];
        double cum = 0.5 * ((double)w + bb[10]) - s;
        acc += ((double)rv - log(cum)) * (double)ev[idx];
    }
    // deterministic block reduce
#pragma unroll
    for (int o = 16; o > 0; o >>= 1) acc += __shfl_down_sync(0xffffffffu, acc, o);
    __shared__ double wred[NW];
    if ((tid & 31) == 0) wred[warp] = acc;
    __syncthreads();
    if (tid == 0) {
        double b = 0.0;
#pragma unroll
        for (int i = 0; i < NW; ++i) b += wred[i];
        g_part[blockIdx.x] = b;
    }
}

// ---------------------------------------------------------------------------
// K5: final deterministic reduce of GBLK partials -> -loss
// ---------------------------------------------------------------------------
__global__ void __launch_bounds__(GBLK) k5_finish(float* __restrict__ out) {
    __shared__ double red[GBLK];
    const int tid = threadIdx.x;
    red[tid] = g_part[tid];
    __syncthreads();
#pragma unroll
    for (int s = GBLK / 2; s > 0; s >>= 1) {
        if (tid < s) red[tid] += red[tid + s];
        __syncthreads();
    }
    if (tid == 0) out[0] = (float)(-red[0]);
}

extern "C" void kernel_launch(void* const* d_in, const int* in_sizes, int n_in,
                              void* d_out, int out_size) {
    const float* risk  = (const float*)d_in[0];
    const float* expr  = (const float*)d_in[1];
    const float* tr    = (const float*)d_in[2];
    const float* ev    = (const float*)d_in[3];
    const float* sigma = (const float*)d_in[4];
    float* out = (float*)d_out;

    k1_pmax<<<GBLK, 256>>>(expr, tr);
    k2_moments<<<GBLK, 256>>>(risk, expr, tr, sigma);
    k3_coeffs<<<1, 320>>>();
    k4_eval<<<GBLK, 256>>>(risk, expr, tr, ev);
    k5_finish<<<1, GBLK>>>(out);
}

// round 3
// speedup vs baseline: 1.6304x; 1.6304x over previous
#include <cuda_runtime.h>
#include <math.h>

#define NN 2048
#define MM 32
#define GRIDA 128
#define GRIDB 128
#define NW 8                    // warps per block (256 threads)
#define RPB (NN / GRIDA)        // 16 rows per block
#define RPW (RPB / NW)          // 2 rows per warp

// ---- scratch (no device allocations allowed) ----
__device__ float  g_pmax[GRIDA][MM];         // per-block per-column max(diff)
__device__ double g_pmom[GRIDA][10][MM];     // per-block raw weighted moments M'_p = sum w*T^p
__device__ float  g_bco[11][MM];             // 0..9: poly coeffs b_m (normalized); 10: W
__device__ float  g_f[MM];                   // per-column factor f = scale * exp(-max(diff))
__device__ float  g_part[GRIDB];             // per-block partial loss
__device__ int    g_cnt1, g_cnt2;            // last-block election counters (reset each run)

// 0.5*erf(d) = sum_n Cn d^(2n+1), |d| <= 0.3536, trunc err < 5e-9
__device__ __constant__ double d_C[5] = {
     0.5641895835477563,
    -0.18806319451591878,
     0.05641895835477563,
    -0.013433085322565627,
     0.0026119888127211866
};

__device__ __forceinline__ double binomd(int n, int k) {
    double r = 1.0;
    for (int i = 1; i <= k; ++i) r = r * (double)(n - k + i) / (double)i;
    return r;
}

// ---------------------------------------------------------------------------
// Kernel A: raw moments + max partials; elected last block builds coefficients.
// Coalesced: lane = column k, (block, warp) = rows.
// ---------------------------------------------------------------------------
__global__ void __launch_bounds__(256) kA(const float* __restrict__ risk,
                                          const float* __restrict__ expr,
                                          const float* __restrict__ tr,
                                          const float* __restrict__ sigma) {
    const int tid  = threadIdx.x;
    const int warp = tid >> 5, lane = tid & 31;
    const int row0 = blockIdx.x * RPB + warp * RPW;

    float  dmax = -1e30f;
    double m[10];
#pragma unroll
    for (int q = 0; q < 10; ++q) m[q] = 0.0;

#pragma unroll
    for (int r = 0; r < RPW; ++r) {
        const int idx = (row0 + r) * MM + lane;
        float diff = expr[idx] - tr[idx];
        float T    = expf(diff);
        float w    = expf(risk[idx]);
        dmax = fmaxf(dmax, diff);
        double Td = (double)T;
        double p  = (double)w;
#pragma unroll
        for (int q = 0; q < 10; ++q) { m[q] += p; p *= Td; }
    }

    __shared__ float  smax[NW][MM];
    __shared__ double smom[NW][10][MM];      // 20 KB
    smax[warp][lane] = dmax;
#pragma unroll
    for (int q = 0; q < 10; ++q) smom[warp][q][lane] = m[q];
    __syncthreads();

    if (warp == 0) {
        float mx = smax[0][lane];
#pragma unroll
        for (int i = 1; i < NW; ++i) mx = fmaxf(mx, smax[i][lane]);
        g_pmax[blockIdx.x][lane] = mx;
    }
    for (int o = tid; o < 320; o += 256) {
        const int q = o >> 5, kk = o & 31;
        double s = smom[0][q][kk];
#pragma unroll
        for (int i = 1; i < NW; ++i) s += smom[i][q][kk];
        g_pmom[blockIdx.x][q][kk] = s;
    }

    // ---- elect last block ----
    __threadfence();
    __syncthreads();
    __shared__ int isLast;
    if (tid == 0) isLast = (atomicAdd(&g_cnt1, 1) == GRIDA - 1);
    __syncthreads();
    if (!isLast) return;
    __threadfence();

    // column max -> f
    __shared__ float sf[MM];
    {
        float mx = -1e30f;
        for (int b = warp; b < GRIDA; b += NW) mx = fmaxf(mx, g_pmax[b][lane]);
        smax[warp][lane] = mx;
        __syncthreads();
        if (warp == 0) {
            float m2 = smax[0][lane];
#pragma unroll
            for (int i = 1; i < NW; ++i) m2 = fmaxf(m2, smax[i][lane]);
            float scale = 1.0f / (2.0f * sigma[0] * sqrtf(2.0f));
            float f = scale * expf(-m2);
            sf[lane] = f;
            g_f[lane] = f;
        }
        __syncthreads();
    }

    // reduce moments, rescale to normalized x-domain: M_p = M'_p * f^p
    __shared__ double Ms[10][MM];
    for (int o = tid; o < 320; o += 256) {
        const int q = o >> 5, kk = o & 31;
        double M = 0.0;
        for (int b = 0; b < GRIDA; ++b) M += g_pmom[b][q][kk];
        double fd = (double)sf[kk], fp = 1.0;
        for (int i = 0; i < q; ++i) fp *= fd;
        Ms[q][kk] = M * fp;
    }
    __syncthreads();

    // b_m = sum_n Cn * binom(2n+1,m) * (-1)^(2n+1-m) * M_(2n+1-m)
    for (int o = tid; o < 320; o += 256) {
        const int mdeg = o >> 5, kk = o & 31;
        double bm = 0.0;
#pragma unroll
        for (int n = 0; n < 5; ++n) {
            const int L = 2 * n + 1;
            if (L >= mdeg) {
                double s = ((L - mdeg) & 1) ? -1.0 : 1.0;
                bm += d_C[n] * binomd(L, mdeg) * s * Ms[L - mdeg][kk];
            }
        }
        g_bco[mdeg][kk] = (float)bm;
        if (mdeg == 0) g_bco[10][kk] = (float)Ms[0][kk];   // W
    }
    __threadfence();
    __syncthreads();
    if (tid == 0) g_cnt1 = 0;    // reset for next graph replay
}

// ---------------------------------------------------------------------------
// Kernel B: per-element eval + loss reduction; elected last block finishes.
//   x = exp(diff)*f;  S = Horner(b, x);  cum = 0.5*(W + w) - S
//   val = (risk - log(cum)) * ev
// ---------------------------------------------------------------------------
__global__ void __launch_bounds__(256) kB(const float* __restrict__ risk,
                                          const float* __restrict__ expr,
                                          const float* __restrict__ tr,
                                          const float* __restrict__ ev,
                                          float* __restrict__ out) {
    const int tid  = threadIdx.x;
    const int warp = tid >> 5, lane = tid & 31;
    const int row0 = blockIdx.x * (NN / GRIDB) + warp * ((NN / GRIDB) / NW);

    float bb[10];
#pragma unroll
    for (int q = 0; q < 10; ++q) bb[q] = g_bco[q][lane];
    const float W = g_bco[10][lane];
    const float f = g_f[lane];

    float acc = 0.0f;
#pragma unroll
    for (int r = 0; r < (NN / GRIDB) / NW; ++r) {
        const int idx = (row0 + r) * MM + lane;
        float rv = risk[idx];
        float w  = expf(rv);
        float x  = expf(expr[idx] - tr[idx]) * f;
        float s  = bb[9];
#pragma unroll
        for (int q = 8; q >= 0; --q) s = fmaf(s, x, bb[q]);
        float cum = fmaf(0.5f, W + w, -s);
        acc += (rv - logf(cum)) * ev[idx];
    }

    // deterministic block reduce
#pragma unroll
    for (int o = 16; o > 0; o >>= 1) acc += __shfl_down_sync(0xffffffffu, acc, o);
    __shared__ float wred[NW];
    if ((tid & 31) == 0) wred[warp] = acc;
    __syncthreads();
    if (tid == 0) {
        float b = 0.0f;
#pragma unroll
        for (int i = 0; i < NW; ++i) b += wred[i];
        g_part[blockIdx.x] = b;
    }

    // ---- elect last block, final reduce ----
    __threadfence();
    __syncthreads();
    __shared__ int isLast;
    if (tid == 0) isLast = (atomicAdd(&g_cnt2, 1) == GRIDB - 1);
    __syncthreads();
    if (!isLast) return;
    __threadfence();

    __shared__ float red[128];
    if (tid < 128) red[tid] = g_part[tid];
    __syncthreads();
#pragma unroll
    for (int s = 64; s > 0; s >>= 1) {
        if (tid < s) red[tid] += red[tid + s];
        __syncthreads();
    }
    if (tid == 0) {
        out[0] = -red[0];
        g_cnt2 = 0;              // reset for next graph replay
    }
}

extern "C" void kernel_launch(void* const* d_in, const int* in_sizes, int n_in,
                              void* d_out, int out_size) {
    const float* risk  = (const float*)d_in[0];
    const float* expr  = (const float*)d_in[1];
    const float* tr    = (const float*)d_in[2];
    const float* ev    = (const float*)d_in[3];
    const float* sigma = (const float*)d_in[4];
    float* out = (float*)d_out;

    kA<<<GRIDA, 256>>>(risk, expr, tr, sigma);
    kB<<<GRIDB, 256>>>(risk, expr, tr, ev, out);
}

// round 4
// speedup vs baseline: 4.9153x; 3.0148x over previous
#include <cuda_runtime.h>
#include <math.h>

#define NN 2048
#define MM 32
#define GA 32                    // kA grid
#define NWA 8                    // kA warps/block (256 threads)
#define RPB_A (NN / GA)          // 64 rows per kA block
#define RPW_A (RPB_A / NWA)      // 8 rows per warp
#define GB 128                   // kB grid
#define TB 512                   // kB threads (16 warps)
#define RPB_B (NN / GB)          // 16 rows per kB block (1 per warp)

// ---- scratch (no device allocations allowed) ----
__device__ float g_pmom[GA][10][MM];   // per-block raw weighted moments M'_p = sum w*T^p
__device__ float g_pmax[GA][MM];       // per-block per-column max(diff)
__device__ float g_part[GB];           // per-block partial loss
__device__ int   g_cnt;                // last-block election counter

// 0.5*erf(d) = sum_n Cn d^(2n+1), |d| <= 0.3536, trunc err < 5e-9
__device__ __constant__ double d_C[5] = {
     0.5641895835477563,
    -0.18806319451591878,
     0.05641895835477563,
    -0.013433085322565627,
     0.0026119888127211866
};
// Pascal rows (only odd n used): BIN[n][k] = binom(n,k)
__device__ __constant__ int d_BIN[10][10] = {
    {1,0,0,0,0,0,0,0,0,0},
    {1,1,0,0,0,0,0,0,0,0},
    {1,2,1,0,0,0,0,0,0,0},
    {1,3,3,1,0,0,0,0,0,0},
    {1,4,6,4,1,0,0,0,0,0},
    {1,5,10,10,5,1,0,0,0,0},
    {1,6,15,20,15,6,1,0,0,0},
    {1,7,21,35,35,21,7,1,0,0},
    {1,8,28,56,70,56,28,8,1,0},
    {1,9,36,84,126,126,84,36,9,1}
};

// ---------------------------------------------------------------------------
// kA: per-block raw moments (fp32) + per-column max(diff). No election.
// Coalesced: lane = column k, (block, warp, r) = rows.
// ---------------------------------------------------------------------------
__global__ void __launch_bounds__(256) kA(const float* __restrict__ risk,
                                          const float* __restrict__ expr,
                                          const float* __restrict__ tr) {
    const int tid  = threadIdx.x;
    const int warp = tid >> 5, lane = tid & 31;
    const int row0 = blockIdx.x * RPB_A + warp * RPW_A;

    float mx = -1e30f;
    float m[10];
#pragma unroll
    for (int q = 0; q < 10; ++q) m[q] = 0.0f;

#pragma unroll
    for (int r = 0; r < RPW_A; ++r) {
        const int idx = (row0 + r) * MM + lane;
        float diff = expr[idx] - tr[idx];
        float T = __expf(diff) ;
        T = expf(diff);                       // accurate exp
        float w = expf(risk[idx]);
        mx = fmaxf(mx, diff);
        float p = w;
        m[0] += p;
#pragma unroll
        for (int q = 1; q < 10; ++q) { p *= T; m[q] += p; }
    }

    __shared__ float smax[NWA][MM];
    __shared__ float smom[NWA][10][MM];     // 10 KB
    smax[warp][lane] = mx;
#pragma unroll
    for (int q = 0; q < 10; ++q) smom[warp][q][lane] = m[q];
    __syncthreads();

    if (warp == 0) {
        float v = smax[0][lane];
#pragma unroll
        for (int i = 1; i < NWA; ++i) v = fmaxf(v, smax[i][lane]);
        g_pmax[blockIdx.x][lane] = v;
    }
    for (int o = tid; o < 320; o += 256) {
        const int q = o >> 5, kk = o & 31;
        float s = smom[0][q][kk];
#pragma unroll
        for (int i = 1; i < NWA; ++i) s += smom[i][q][kk];
        g_pmom[blockIdx.x][q][kk] = s;
    }
}

// ---------------------------------------------------------------------------
// kB: every block redundantly reduces partials -> coefficients (cheap),
//     then evaluates its 16 rows, reduces loss, elected last block finishes.
// ---------------------------------------------------------------------------
__global__ void __launch_bounds__(TB) kB(const float* __restrict__ risk,
                                         const float* __restrict__ expr,
                                         const float* __restrict__ tr,
                                         const float* __restrict__ ev,
                                         const float* __restrict__ sigma,
                                         float* __restrict__ out) {
    const int tid  = threadIdx.x;
    const int warp = tid >> 5, lane = tid & 31;

    __shared__ float  sscale;
    __shared__ float  sf[MM];          // per-column factor f = scale*exp(-max)
    __shared__ double sM[10][MM];      // normalized moments
    __shared__ float  sbb[11][MM];     // poly coeffs b_0..b_9, row 10 = W

    if (tid == 0) sscale = 1.0f / (2.0f * sigma[0] * sqrtf(2.0f));
    __syncthreads();

    // column max -> f
    if (tid < MM) {
        float v = g_pmax[0][tid];
#pragma unroll
        for (int b = 1; b < GA; ++b) v = fmaxf(v, g_pmax[b][tid]);
        sf[tid] = sscale * expf(-v);
    }
    // raw moment reduce (tid < 320, one output each)
    double M = 0.0;
    if (tid < 320) {
        const int q = tid >> 5, kk = tid & 31;
        float s = 0.0f;
#pragma unroll
        for (int b = 0; b < GA; ++b) s += g_pmom[b][q][kk];
        M = (double)s;
    }
    __syncthreads();
    // rescale to normalized domain: M_q = M'_q * f^q
    if (tid < 320) {
        const int q = tid >> 5, kk = tid & 31;
        double fd = (double)sf[kk], fp = 1.0;
#pragma unroll
        for (int i = 0; i < 9; ++i) if (i < q) fp *= fd;
        sM[q][kk] = M * fp;
    }
    __syncthreads();
    // b_m = sum_{p: m+p odd <= 9} C[(m+p)>>1] * binom(m+p, m) * (-1)^p * M_p
    if (tid < 320) {
        const int m = tid >> 5, kk = tid & 31;
        double bm = 0.0;
#pragma unroll
        for (int p = 0; p < 10; ++p) {
            const int L = m + p;
            if ((L & 1) && L <= 9) {
                double t = d_C[L >> 1] * (double)d_BIN[L][m] * sM[p][kk];
                bm += (p & 1) ? -t : t;
            }
        }
        sbb[m][kk] = (float)bm;
        if (m == 0) sbb[10][kk] = (float)sM[0][kk];   // W
    }
    __syncthreads();

    // ---- eval: one row per warp, lane = column ----
    float bb[10];
#pragma unroll
    for (int q = 0; q < 10; ++q) bb[q] = sbb[q][lane];
    const float W = sbb[10][lane];
    const float f = sf[lane];

    const int idx = (blockIdx.x * RPB_B + warp) * MM + lane;
    float rv = risk[idx];
    float w  = expf(rv);
    float x  = expf(expr[idx] - tr[idx]) * f;
    float s  = bb[9];
#pragma unroll
    for (int q = 8; q >= 0; --q) s = fmaf(s, x, bb[q]);
    float cum = fmaf(0.5f, W + w, -s);
    float val = (rv - logf(cum)) * ev[idx];

    // deterministic block reduce
#pragma unroll
    for (int o = 16; o > 0; o >>= 1) val += __shfl_down_sync(0xffffffffu, val, o);
    __shared__ float wred[TB / 32];
    if (lane == 0) wred[warp] = val;
    __syncthreads();
    if (tid == 0) {
        float b = 0.0f;
#pragma unroll
        for (int i = 0; i < TB / 32; ++i) b += wred[i];
        g_part[blockIdx.x] = b;
    }

    // ---- elect last block, final reduce ----
    __threadfence();
    __syncthreads();
    __shared__ int isLast;
    if (tid == 0) isLast = (atomicAdd(&g_cnt, 1) == GB - 1);
    __syncthreads();
    if (!isLast) return;
    __threadfence();

    __shared__ float red[GB];
    if (tid < GB) red[tid] = g_part[tid];
    __syncthreads();
#pragma unroll
    for (int s2 = GB / 2; s2 > 0; s2 >>= 1) {
        if (tid < s2) red[tid] += red[tid + s2];
        __syncthreads();
    }
    if (tid == 0) {
        out[0] = -red[0];
        g_cnt = 0;               // reset for next graph replay
    }
}

extern "C" void kernel_launch(void* const* d_in, const int* in_sizes, int n_in,
                              void* d_out, int out_size) {
    const float* risk  = (const float*)d_in[0];
    const float* expr  = (const float*)d_in[1];
    const float* tr    = (const float*)d_in[2];
    const float* ev    = (const float*)d_in[3];
    const float* sigma = (const float*)d_in[4];
    float* out = (float*)d_out;

    kA<<<GA, 256>>>(risk, expr, tr);
    kB<<<GB, TB>>>(risk, expr, tr, ev, sigma, out);
}

// round 5
// speedup vs baseline: 5.0108x; 1.0194x over previous
#include <cuda_runtime.h>
#include <math.h>

#define NN 2048
#define MM 32
#define GA 32                    // grid (co-resident -> spin barrier safe)
#define TB 1024                  // threads per block (32 warps)
#define NWB 32                   // warps per block
#define RPB (NN / GA)            // 64 rows per block
#define RPT 2                    // rows (elements) per thread: 64 rows / 32 warps = 2

// ---- scratch (no device allocations allowed) ----
__device__ float g_pmom[GA][10][MM];   // per-block raw weighted moments
__device__ float g_pmax[GA][MM];       // per-block per-column max(diff)
__device__ float g_part[GA];           // per-block partial loss
__device__ volatile int g_bar;         // grid barrier counter
__device__ int   g_cnt;                // final-election counter

// 0.5*erf(d) = sum_n Cn d^(2n+1), |d| <= 0.3536, trunc err < 5e-9
__device__ __constant__ double d_C[5] = {
     0.5641895835477563,
    -0.18806319451591878,
     0.05641895835477563,
    -0.013433085322565627,
     0.0026119888127211866
};
// BIN[n][k] = binom(n,k) (only odd n used)
__device__ __constant__ int d_BIN[10][10] = {
    {1,0,0,0,0,0,0,0,0,0},
    {1,1,0,0,0,0,0,0,0,0},
    {1,2,1,0,0,0,0,0,0,0},
    {1,3,3,1,0,0,0,0,0,0},
    {1,4,6,4,1,0,0,0,0,0},
    {1,5,10,10,5,1,0,0,0,0},
    {1,6,15,20,15,6,1,0,0,0},
    {1,7,21,35,35,21,7,1,0,0},
    {1,8,28,56,70,56,28,8,1,0},
    {1,9,36,84,126,126,84,36,9,1}
};

__global__ void __launch_bounds__(TB, 1) fused(const float* __restrict__ risk,
                                               const float* __restrict__ expr,
                                               const float* __restrict__ tr,
                                               const float* __restrict__ ev,
                                               const float* __restrict__ sigma,
                                               float* __restrict__ out) {
    const int tid  = threadIdx.x;
    const int warp = tid >> 5, lane = tid & 31;
    const int row0 = blockIdx.x * RPB + warp * RPT;

    __shared__ float  smom[NWB][10][MM];   // 40 KB
    __shared__ float  smax[NWB][MM];       // 4 KB
    __shared__ float  sf[MM];
    __shared__ double sM[10][MM];
    __shared__ float  sbb[11][MM];
    __shared__ float  wred[NWB];
    __shared__ int    sflag;

    // ---------------- Phase 1: moments + max; keep values live ----------------
    float rv[RPT], w[RPT], T[RPT], evv[RPT];
    float mx = -1e30f;
    float m[10];
#pragma unroll
    for (int q = 0; q < 10; ++q) m[q] = 0.0f;

#pragma unroll
    for (int r = 0; r < RPT; ++r) {
        const int idx = (row0 + r) * MM + lane;
        rv[r]  = risk[idx];
        float d = expr[idx] - tr[idx];
        evv[r] = ev[idx];
        T[r]   = expf(d);
        w[r]   = expf(rv[r]);
        mx     = fmaxf(mx, d);
        float p = w[r];
        m[0] += p;
#pragma unroll
        for (int q = 1; q < 10; ++q) { p *= T[r]; m[q] += p; }
    }
    smax[warp][lane] = mx;
#pragma unroll
    for (int q = 0; q < 10; ++q) smom[warp][q][lane] = m[q];
    __syncthreads();

    if (warp == 0) {
        float v = smax[0][lane];
#pragma unroll
        for (int i = 1; i < NWB; ++i) v = fmaxf(v, smax[i][lane]);
        g_pmax[blockIdx.x][lane] = v;
    }
    if (tid < 320) {
        const int q = tid >> 5, kk = tid & 31;
        float s = smom[0][q][kk];
#pragma unroll
        for (int i = 1; i < NWB; ++i) s += smom[i][q][kk];
        g_pmom[blockIdx.x][q][kk] = s;
    }

    // ---------------- Grid barrier ----------------
    __threadfence();
    __syncthreads();
    if (tid == 0) {
        atomicAdd((int*)&g_bar, 1);
        while (g_bar < GA) { __nanosleep(32); }
        __threadfence();
    }
    __syncthreads();

    // ---------------- Phase 2: redundant coefficient build ----------------
    if (tid == 0) sflag = 0;   // reuse later; also compute scale here
    if (tid < MM) {
        float v = g_pmax[0][tid];
#pragma unroll
        for (int b = 1; b < GA; ++b) v = fmaxf(v, g_pmax[b][tid]);
        float scale = 1.0f / (2.0f * sigma[0] * sqrtf(2.0f));
        sf[tid] = scale * expf(-v);
    }
    __syncthreads();
    if (tid < 320) {
        const int q = tid >> 5, kk = tid & 31;
        float s = 0.0f;
#pragma unroll
        for (int b = 0; b < GA; ++b) s += g_pmom[b][q][kk];
        // rescale raw moment into normalized x-domain: M_q = M'_q * f^q
        double fd = (double)sf[kk], fp = 1.0;
#pragma unroll
        for (int i = 0; i < 9; ++i) if (i < q) fp *= fd;
        sM[q][kk] = (double)s * fp;
    }
    __syncthreads();
    if (tid < 320) {
        const int md = tid >> 5, kk = tid & 31;
        double bm = 0.0;
#pragma unroll
        for (int p = 0; p < 10; ++p) {
            const int L = md + p;
            if ((L & 1) && L <= 9) {
                double t = d_C[L >> 1] * (double)d_BIN[L][md] * sM[p][kk];
                bm += (p & 1) ? -t : t;
            }
        }
        sbb[md][kk] = (float)bm;
        if (md == 0) sbb[10][kk] = (float)sM[0][kk];   // W
    }
    __syncthreads();

    // ---------------- Phase 3: eval (registers still live) ----------------
    float bb[10];
#pragma unroll
    for (int q = 0; q < 10; ++q) bb[q] = sbb[q][lane];
    const float W = sbb[10][lane];
    const float f = sf[lane];

    float acc = 0.0f;
#pragma unroll
    for (int r = 0; r < RPT; ++r) {
        float x = T[r] * f;
        float s = bb[9];
#pragma unroll
        for (int q = 8; q >= 0; --q) s = fmaf(s, x, bb[q]);
        float cum = fmaf(0.5f, W + w[r], -s);
        acc += (rv[r] - logf(cum)) * evv[r];
    }
#pragma unroll
    for (int o = 16; o > 0; o >>= 1) acc += __shfl_down_sync(0xffffffffu, acc, o);
    if (lane == 0) wred[warp] = acc;
    __syncthreads();
    if (tid == 0) {
        float b = 0.0f;
#pragma unroll
        for (int i = 0; i < NWB; ++i) b += wred[i];
        g_part[blockIdx.x] = b;
        __threadfence();
        sflag = (atomicAdd(&g_cnt, 1) == GA - 1);
    }
    __syncthreads();
    if (!sflag) return;

    // ---------------- Elected last block: final reduce + reset ----------------
    __threadfence();
    if (tid == 0) {
        float s = 0.0f;
#pragma unroll
        for (int i = 0; i < GA; ++i) s += g_part[i];
        out[0] = -s;
        g_cnt = 0;
        g_bar = 0;               // safe: all blocks already passed both counters
    }
}

extern "C" void kernel_launch(void* const* d_in, const int* in_sizes, int n_in,
                              void* d_out, int out_size) {
    const float* risk  = (const float*)d_in[0];
    const float* expr  = (const float*)d_in[1];
    const float* tr    = (const float*)d_in[2];
    const float* ev    = (const float*)d_in[3];
    const float* sigma = (const float*)d_in[4];
    float* out = (float*)d_out;

    fused<<<GA, TB>>>(risk, expr, tr, ev, sigma, out);
}

// round 6
// speedup vs baseline: 6.1538x; 1.2281x over previous
#include <cuda_runtime.h>
#include <math.h>

#define NN 2048
#define MM 32
#define GA 32                    // grid (co-resident on 148 SMs -> spin barrier safe)
#define TB 1024                  // threads per block (32 warps)
#define NWB 32                   // warps per block
#define RPB (NN / GA)            // 64 rows per block
#define RPT 2                    // rows per thread

// ---- scratch (no device allocations allowed) ----
__device__ float g_pmom[GA][10][MM];   // per-block raw weighted moments
__device__ float g_pmax[GA][MM];       // per-block per-column max(diff)
__device__ float g_part[GA];           // per-block partial loss
__device__ volatile int g_bar;         // grid barrier counter
__device__ int   g_cnt;                // final-election counter

// A[m][p] = C[(m+p)/2] * binom(m+p, m) * (-1)^p  for (m+p) odd <= 9, else 0.
// b_m = sum_p A[m][p] * Mn_p, with Mn_p = M'_p * f^p. Precomputed in fp64 on host.
__device__ __constant__ float d_A[10][10] = {
  {0.f,-0.5641895835477563f,0.f, 0.18806319451591878f,0.f,-0.05641895835477563f,0.f, 0.013433085322565627f,0.f,-0.0026119888127211866f},
  {0.5641895835477563f,0.f,-0.5641895835477563f,0.f, 0.28209479177387815f,0.f,-0.09403159725795939f,0.f, 0.023507899314490679f,0.f},
  {0.f, 0.5641895835477563f,0.f,-0.5641895835477563f,0.f, 0.28209479177387817f,0.f,-0.09403159725796272f,0.f,0.f},
  {-0.18806319451591878f,0.f, 0.5641895835477563f,0.f,-0.47015798628979696f,0.f, 0.21940705866857968f,0.f,0.f,0.f},
  {0.f,-0.28209479177387815f,0.f, 0.47015798628979696f,0.f,-0.32911059040286952f,0.f,0.f,0.f,0.f},
  {0.05641895835477563f,0.f,-0.28209479177387817f,0.f, 0.32911059040286952f,0.f,0.f,0.f,0.f,0.f},
  {0.f, 0.09403159725795939f,0.f,-0.21940705866857968f,0.f,0.f,0.f,0.f,0.f,0.f},
  {-0.013433085322565627f,0.f, 0.09403159725796272f,0.f,0.f,0.f,0.f,0.f,0.f,0.f},
  {0.f,-0.023507899314490679f,0.f,0.f,0.f,0.f,0.f,0.f,0.f,0.f},
  {0.0026119888127211866f,0.f,0.f,0.f,0.f,0.f,0.f,0.f,0.f,0.f}
};

__global__ void __launch_bounds__(TB, 1) fused(const float* __restrict__ risk,
                                               const float* __restrict__ expr,
                                               const float* __restrict__ tr,
                                               const float* __restrict__ ev,
                                               const float* __restrict__ sigma,
                                               float* __restrict__ out) {
    const int tid  = threadIdx.x;
    const int warp = tid >> 5, lane = tid & 31;
    const int row0 = blockIdx.x * RPB + warp * RPT;

    __shared__ float smom[NWB][10][MM];   // 40 KB
    __shared__ float smax[NWB][MM];       // 4 KB
    __shared__ float sf[MM];
    __shared__ float sM[10][MM];          // normalized moments Mn
    __shared__ float sbb[11][MM];         // b_0..b_9, row 10 = W
    __shared__ float wred[NWB];
    __shared__ int   sflag;

    const float sigv = sigma[0];          // issue early, used after barrier

    // ---------------- Phase 1: moments + max; keep element values live ----------------
    float rv[RPT], w[RPT], T[RPT], evv[RPT];
    float mx = -1e30f;
    float m[10];
#pragma unroll
    for (int q = 0; q < 10; ++q) m[q] = 0.0f;

#pragma unroll
    for (int r = 0; r < RPT; ++r) {
        const int idx = (row0 + r) * MM + lane;
        rv[r]  = risk[idx];
        float d = expr[idx] - tr[idx];
        evv[r] = ev[idx];
        T[r]   = __expf(d);
        w[r]   = __expf(rv[r]);
        mx     = fmaxf(mx, d);
        float p = w[r];
        m[0] += p;
#pragma unroll
        for (int q = 1; q < 10; ++q) { p *= T[r]; m[q] += p; }
    }
    smax[warp][lane] = mx;
#pragma unroll
    for (int q = 0; q < 10; ++q) smom[warp][q][lane] = m[q];
    __syncthreads();

    if (warp == 0) {
        float v = smax[0][lane];
#pragma unroll
        for (int i = 1; i < NWB; ++i) v = fmaxf(v, smax[i][lane]);
        g_pmax[blockIdx.x][lane] = v;
    }
    if (tid < 320) {
        const int q = tid >> 5, kk = tid & 31;
        float s = smom[0][q][kk];
#pragma unroll
        for (int i = 1; i < NWB; ++i) s += smom[i][q][kk];
        g_pmom[blockIdx.x][q][kk] = s;
    }

    // ---------------- Grid barrier ----------------
    __threadfence();
    __syncthreads();
    if (tid == 0) {
        sflag = 0;
        atomicAdd((int*)&g_bar, 1);
        while (g_bar < GA) { __nanosleep(32); }
        __threadfence();
    }
    __syncthreads();

    // ---------------- Phase 2: fp32 coefficient build (redundant per block) ----------
    if (tid < MM) {
        float v = g_pmax[0][tid];
#pragma unroll
        for (int b = 1; b < GA; ++b) v = fmaxf(v, g_pmax[b][tid]);
        float scale = 1.0f / (2.0f * sigv * sqrtf(2.0f));
        sf[tid] = scale * __expf(-v);
    }
    __syncthreads();
    if (tid < 320) {
        const int q = tid >> 5, kk = tid & 31;
        float s = 0.0f;
#pragma unroll
        for (int b = 0; b < GA; ++b) s += g_pmom[b][q][kk];
        float f = sf[kk], fp = 1.0f;
#pragma unroll
        for (int i = 0; i < 9; ++i) if (i < q) fp *= f;
        sM[q][kk] = s * fp;                       // Mn_q = M'_q * f^q
    }
    __syncthreads();
    if (tid < 320) {
        const int md = tid >> 5, kk = tid & 31;
        float bm = 0.0f;
#pragma unroll
        for (int p = 0; p < 10; ++p) bm = fmaf(d_A[md][p], sM[p][kk], bm);
        sbb[md][kk] = bm;
        if (md == 0) sbb[10][kk] = sM[0][kk];     // W
    }
    __syncthreads();

    // ---------------- Phase 3: eval (element values still in registers) -------------
    float bb[10];
#pragma unroll
    for (int q = 0; q < 10; ++q) bb[q] = sbb[q][lane];
    const float W = sbb[10][lane];
    const float f = sf[lane];

    float acc = 0.0f;
#pragma unroll
    for (int r = 0; r < RPT; ++r) {
        float x = T[r] * f;
        float s = bb[9];
#pragma unroll
        for (int q = 8; q >= 0; --q) s = fmaf(s, x, bb[q]);
        float cum = fmaf(0.5f, W + w[r], -s);
        acc += (rv[r] - __logf(cum)) * evv[r];
    }
#pragma unroll
    for (int o = 16; o > 0; o >>= 1) acc += __shfl_down_sync(0xffffffffu, acc, o);
    if (lane == 0) wred[warp] = acc;
    __syncthreads();
    if (tid == 0) {
        float b = 0.0f;
#pragma unroll
        for (int i = 0; i < NWB; ++i) b += wred[i];
        g_part[blockIdx.x] = b;
        __threadfence();
        sflag = (atomicAdd(&g_cnt, 1) == GA - 1);
    }
    __syncthreads();
    if (!sflag) return;

    // ---------------- Elected last block: warp-parallel final reduce + reset --------
    __threadfence();
    if (warp == 0) {
        float v = g_part[lane];                   // GA == 32 partials
#pragma unroll
        for (int o = 16; o > 0; o >>= 1) v += __shfl_down_sync(0xffffffffu, v, o);
        if (lane == 0) {
            out[0] = -v;
            g_cnt = 0;
            g_bar = 0;          // safe: all blocks already passed both counters
        }
    }
}

extern "C" void kernel_launch(void* const* d_in, const int* in_sizes, int n_in,
                              void* d_out, int out_size) {
    const float* risk  = (const float*)d_in[0];
    const float* expr  = (const float*)d_in[1];
    const float* tr    = (const float*)d_in[2];
    const float* ev    = (const float*)d_in[3];
    const float* sigma = (const float*)d_in[4];
    float* out = (float*)d_out;

    fused<<<GA, TB>>>(risk, expr, tr, ev, sigma, out);
}